// round 14
// baseline (speedup 1.0000x reference)
#include <cuda_runtime.h>
#include <math.h>

// iNGPDW: fused hash-grid encode + erf scaling + 40->64->64->13 SELU MLP.
// Warp-tiled GEMM MLP: each warp stages its 32 points' activations in a
// per-warp smem tile [64 k][32 pt (padded to 36)]; each thread computes an
// 8-pt x 8-j register block with packed fma.rn.f32x2. One LDS.128 feeds 32
// FFMA2. Tile rows padded 32->36 floats so the per-row stride rotates banks
// (kills the 8-way STS conflict on layer outputs). Warp-private tile:
// __syncwarp only. SELU uses expm1f (cancellation-safe).
// NOTE: requires cudaFuncSetAttribute for >48KB dynamic smem (round-6 failure).

constexpr int NLEV = 10;
constexpr int TBL  = 1 << 16;
constexpr int HIDN = 64;
constexpr int OUTD = 13;
constexpr int BLK  = 128;            // 4 warps
constexpr int ROWP = 36;             // padded row length (floats)
constexpr int TILE = HIDN * ROWP;    // floats per warp tile

struct ResParams { int res[NLEV]; };

typedef unsigned long long u64;

__device__ __forceinline__ u64 pk2(float lo, float hi) {
    u64 r; asm("mov.b64 %0, {%1, %2};" : "=l"(r) : "f"(lo), "f"(hi)); return r;
}
__device__ __forceinline__ u64 dup2(float v) {
    u64 r; asm("mov.b64 %0, {%1, %1};" : "=l"(r) : "f"(v)); return r;
}
__device__ __forceinline__ void upk2(u64 v, float& lo, float& hi) {
    asm("mov.b64 {%0, %1}, %2;" : "=f"(lo), "=f"(hi) : "l"(v));
}
__device__ __forceinline__ void fma2(u64& acc, u64 a, u64 b) {
    asm("fma.rn.f32x2 %0, %1, %2, %0;" : "+l"(acc) : "l"(a), "l"(b));
}

__device__ __forceinline__ float selu_f(float v) {
    const float sc = 1.0507009873554805f;
    const float al = 1.6732632423543772f;
    return v > 0.0f ? sc * v : sc * (al * expm1f(v));
}

__global__ __launch_bounds__(BLK, 3)
void ngp_fused7_kernel(const float*  __restrict__ gx,     // [N,3]
                       const float*  __restrict__ gcr,    // [N]
                       const float4* __restrict__ gtab,   // [NLEV*TBL] float4
                       const float*  __restrict__ gW1,    // [40,64]
                       const float*  __restrict__ gb1,    // [64]
                       const float*  __restrict__ gW2,    // [64,64]
                       const float*  __restrict__ gb2,    // [64]
                       const float*  __restrict__ gW3,    // [64,13]
                       const float*  __restrict__ gb3,    // [13]
                       float*        __restrict__ gout,   // [N,13]
                       int N, ResParams rp)
{
    __shared__ float sW1[40 * HIDN];      // natural [k][j]
    __shared__ float sW2[HIDN * HIDN];
    __shared__ float sW3[HIDN * 16];      // rows padded 13 -> 16
    __shared__ float sB1[HIDN];
    __shared__ float sB2[HIDN];
    __shared__ float sB3[16];
    extern __shared__ float sT[];         // [4 warps][64][36] = 36 KB

    const int tid = threadIdx.x;
    for (int i = tid; i < 40 * HIDN; i += BLK) sW1[i] = gW1[i];
    for (int i = tid; i < HIDN * HIDN; i += BLK) sW2[i] = gW2[i];
    for (int i = tid; i < HIDN * 16; i += BLK) {
        int k = i >> 4, j = i & 15;
        sW3[i] = (j < OUTD) ? gW3[k * OUTD + j] : 0.0f;
    }
    if (tid < HIDN) { sB1[tid] = gb1[tid]; sB2[tid] = gb2[tid]; }
    if (tid < 16)   { sB3[tid] = (tid < OUTD) ? gb3[tid] : 0.0f; }
    __syncthreads();

    const int lane = tid & 31;
    const int wrp  = tid >> 5;
    float* tile = sT + wrp * TILE;
    const int warpBase = blockIdx.x * BLK + wrp * 32;

    // ================= encoding: point n = warpBase + lane =================
    {
        const int nr = warpBase + lane;
        const int n = (nr < N) ? nr : (N - 1);
        const float x0 = gx[3 * n + 0];
        const float x1 = gx[3 * n + 1];
        const float x2 = gx[3 * n + 2];
        const float crs = gcr[n] * 0.5f;

        #pragma unroll
        for (int l = 0; l < NLEV; l++) {
            const float rf = (float)rp.res[l];
            const float xs0 = x0 * rf, xs1 = x1 * rf, xs2 = x2 * rf;
            const float fb0 = floorf(xs0), fb1 = floorf(xs1), fb2 = floorf(xs2);
            const float f0 = xs0 - fb0, f1 = xs1 - fb1, f2 = xs2 - fb2;
            const float g0 = 1.0f - f0, g1 = 1.0f - f1, g2 = 1.0f - f2;
            const unsigned c0 = (unsigned)fb0, c1 = (unsigned)fb1, c2 = (unsigned)fb2;

            const unsigned hx0 = c0,               hx1 = c0 + 1u;
            const unsigned hy0 = c1 * 2654435761u, hy1 = hy0 + 2654435761u;
            const unsigned hz0 = c2 * 805459861u,  hz1 = hz0 + 805459861u;
            const float wyz00 = g1 * g2, wyz01 = g1 * f2;
            const float wyz10 = f1 * g2, wyz11 = f1 * f2;

            const float4* tb = gtab + (unsigned)(l * TBL);
            float a0 = 0.f, a1 = 0.f, a2 = 0.f, a3 = 0.f;
            #pragma unroll
            for (int c = 0; c < 8; c++) {
                const unsigned hx = (c & 4) ? hx1 : hx0;
                const unsigned hy = (c & 2) ? hy1 : hy0;
                const unsigned hz = (c & 1) ? hz1 : hz0;
                const unsigned idx = (hx ^ hy ^ hz) & (unsigned)(TBL - 1);
                const float4 t = __ldg(&tb[idx]);
                const float wyz = (c & 2) ? ((c & 1) ? wyz11 : wyz10)
                                          : ((c & 1) ? wyz01 : wyz00);
                const float w = ((c & 4) ? f0 : g0) * wyz;
                a0 = fmaf(w, t.x, a0);
                a1 = fmaf(w, t.y, a1);
                a2 = fmaf(w, t.z, a2);
                a3 = fmaf(w, t.w, a3);
            }
            float scal;
            if (l == 0) scal = 1.0f;      // erf(1/sqrt(1e-12)) == 1 in fp32
            else        scal = erff(rsqrtf(fmaxf((8.0f * (float)l) * crs, 1e-12f)));
            tile[(0 * 10 + l) * ROWP + lane] = a0 * scal;
            tile[(1 * 10 + l) * ROWP + lane] = a1 * scal;
            tile[(2 * 10 + l) * ROWP + lane] = a2 * scal;
            tile[(3 * 10 + l) * ROWP + lane] = a3 * scal;
        }
    }
    __syncwarp();

    // ================= warp-tiled MLP =================
    const int pg = lane >> 3;   // point group: points pg*8 .. pg*8+7
    const int jg = lane & 7;    // j group:     j      jg*8 .. jg*8+7
    const float* arow = tile + pg * 8;

    // ---- layer 1: 40 -> 64, SELU ----
    {
        u64 acc[8][4];
        {
            const u64* bp = reinterpret_cast<const u64*>(&sB1[jg * 8]);
            const u64 b0 = bp[0], b1 = bp[1], b2 = bp[2], b3 = bp[3];
            #pragma unroll
            for (int pp = 0; pp < 8; pp++) {
                acc[pp][0] = b0; acc[pp][1] = b1; acc[pp][2] = b2; acc[pp][3] = b3;
            }
        }
        #pragma unroll 8
        for (int k = 0; k < 40; k++) {
            const float4 a0 = *reinterpret_cast<const float4*>(arow + k * ROWP);
            const float4 a1 = *reinterpret_cast<const float4*>(arow + k * ROWP + 4);
            const u64* wr = reinterpret_cast<const u64*>(&sW1[k * HIDN + jg * 8]);
            const u64 w0 = wr[0], w1 = wr[1], w2 = wr[2], w3 = wr[3];
            const float av[8] = {a0.x, a0.y, a0.z, a0.w, a1.x, a1.y, a1.z, a1.w};
            #pragma unroll
            for (int pp = 0; pp < 8; pp++) {
                const u64 d = dup2(av[pp]);
                fma2(acc[pp][0], d, w0);
                fma2(acc[pp][1], d, w1);
                fma2(acc[pp][2], d, w2);
                fma2(acc[pp][3], d, w3);
            }
        }
        __syncwarp();   // all lanes done reading rows before overwrite
        float o[8][8];  // [jj][pp]
        #pragma unroll
        for (int pp = 0; pp < 8; pp++) {
            #pragma unroll
            for (int q = 0; q < 4; q++) {
                float s0, s1; upk2(acc[pp][q], s0, s1);
                o[2 * q + 0][pp] = selu_f(s0);
                o[2 * q + 1][pp] = selu_f(s1);
            }
        }
        #pragma unroll
        for (int jj = 0; jj < 8; jj++) {
            u64* dst = reinterpret_cast<u64*>(tile + (jg * 8 + jj) * ROWP + pg * 8);
            #pragma unroll
            for (int t = 0; t < 4; t++)
                dst[t] = pk2(o[jj][2 * t], o[jj][2 * t + 1]);
        }
        __syncwarp();
    }

    // ---- layer 2: 64 -> 64, SELU ----
    {
        u64 acc[8][4];
        {
            const u64* bp = reinterpret_cast<const u64*>(&sB2[jg * 8]);
            const u64 b0 = bp[0], b1 = bp[1], b2 = bp[2], b3 = bp[3];
            #pragma unroll
            for (int pp = 0; pp < 8; pp++) {
                acc[pp][0] = b0; acc[pp][1] = b1; acc[pp][2] = b2; acc[pp][3] = b3;
            }
        }
        #pragma unroll 8
        for (int k = 0; k < HIDN; k++) {
            const float4 a0 = *reinterpret_cast<const float4*>(arow + k * ROWP);
            const float4 a1 = *reinterpret_cast<const float4*>(arow + k * ROWP + 4);
            const u64* wr = reinterpret_cast<const u64*>(&sW2[k * HIDN + jg * 8]);
            const u64 w0 = wr[0], w1 = wr[1], w2 = wr[2], w3 = wr[3];
            const float av[8] = {a0.x, a0.y, a0.z, a0.w, a1.x, a1.y, a1.z, a1.w};
            #pragma unroll
            for (int pp = 0; pp < 8; pp++) {
                const u64 d = dup2(av[pp]);
                fma2(acc[pp][0], d, w0);
                fma2(acc[pp][1], d, w1);
                fma2(acc[pp][2], d, w2);
                fma2(acc[pp][3], d, w3);
            }
        }
        __syncwarp();
        float o[8][8];
        #pragma unroll
        for (int pp = 0; pp < 8; pp++) {
            #pragma unroll
            for (int q = 0; q < 4; q++) {
                float s0, s1; upk2(acc[pp][q], s0, s1);
                o[2 * q + 0][pp] = selu_f(s0);
                o[2 * q + 1][pp] = selu_f(s1);
            }
        }
        #pragma unroll
        for (int jj = 0; jj < 8; jj++) {
            u64* dst = reinterpret_cast<u64*>(tile + (jg * 8 + jj) * ROWP + pg * 8);
            #pragma unroll
            for (int t = 0; t < 4; t++)
                dst[t] = pk2(o[jj][2 * t], o[jj][2 * t + 1]);
        }
        __syncwarp();
    }

    // ---- layer 3: 64 -> 13 (rows padded to 16). Thread j = jg*2, jg*2+1 ----
    {
        u64 acc3[8];
        {
            const u64 b = *reinterpret_cast<const u64*>(&sB3[jg * 2]);
            #pragma unroll
            for (int pp = 0; pp < 8; pp++) acc3[pp] = b;
        }
        #pragma unroll 8
        for (int k = 0; k < HIDN; k++) {
            const float4 a0 = *reinterpret_cast<const float4*>(arow + k * ROWP);
            const float4 a1 = *reinterpret_cast<const float4*>(arow + k * ROWP + 4);
            const u64 w = *reinterpret_cast<const u64*>(&sW3[k * 16 + jg * 2]);
            const float av[8] = {a0.x, a0.y, a0.z, a0.w, a1.x, a1.y, a1.z, a1.w};
            #pragma unroll
            for (int pp = 0; pp < 8; pp++) {
                const u64 d = dup2(av[pp]);
                fma2(acc3[pp], d, w);
            }
        }
        const int j0 = jg * 2;
        #pragma unroll
        for (int pp = 0; pp < 8; pp++) {
            const int np = warpBase + pg * 8 + pp;
            if (np < N && j0 < OUTD) {
                float s0, s1; upk2(acc3[pp], s0, s1);
                float* op = gout + (size_t)np * OUTD;
                op[j0] = s0;
                if (j0 + 1 < OUTD) op[j0 + 1] = s1;
            }
        }
    }
}

extern "C" void kernel_launch(void* const* d_in, const int* in_sizes, int n_in,
                              void* d_out, int out_size) {
    const float*  x   = (const float*)d_in[0];
    const float*  cr  = (const float*)d_in[1];
    const float4* tab = (const float4*)d_in[2];
    const float*  W1  = (const float*)d_in[3];
    const float*  b1  = (const float*)d_in[4];
    const float*  W2  = (const float*)d_in[5];
    const float*  b2  = (const float*)d_in[6];
    const float*  W3  = (const float*)d_in[7];
    const float*  b3  = (const float*)d_in[8];
    float* out = (float*)d_out;

    const int N = in_sizes[0] / 3;

    // Reference resolutions, identical libm double sequence.
    ResParams rp;
    const double B = exp((log(16.0 * pow(2.0, 10.0)) - log(16.0)) / 9.0);
    for (int l = 0; l < NLEV; l++) {
        rp.res[l] = (int)floor(16.0 * pow(B, (double)l));
    }

    const int dynSmem = 4 * TILE * (int)sizeof(float);   // 36 KB
    static bool attr_set = false;
    if (!attr_set) {
        cudaFuncSetAttribute(ngp_fused7_kernel,
                             cudaFuncAttributeMaxDynamicSharedMemorySize, dynSmem);
        attr_set = true;
    }

    const int blocks = (N + BLK - 1) / BLK;
    ngp_fused7_kernel<<<blocks, BLK, dynSmem>>>(
        x, cr, tab, W1, b1, W2, b2, W3, b3, out, N, rp);
}

// round 15
// speedup vs baseline: 1.0005x; 1.0005x over previous
#include <cuda_runtime.h>
#include <math.h>

// iNGPDW: fused hash-grid encode + erf scaling + 40->64->64->13 SELU MLP.
// Warp-tiled GEMM MLP: each warp stages its 32 points' activations in a
// per-warp smem tile [64 k][32 pt (padded to 36)]; each thread computes an
// 8-pt x 8-j register block with packed fma.rn.f32x2. One LDS.128 feeds 32
// FFMA2. Tile rows padded 32->36 floats so the per-row stride rotates banks
// (kills the 8-way STS conflict on layer outputs). Warp-private tile:
// __syncwarp only. SELU uses expm1f (cancellation-safe).
// NOTE: requires cudaFuncSetAttribute for >48KB dynamic smem (round-6 failure).

constexpr int NLEV = 10;
constexpr int TBL  = 1 << 16;
constexpr int HIDN = 64;
constexpr int OUTD = 13;
constexpr int BLK  = 128;            // 4 warps
constexpr int ROWP = 36;             // padded row length (floats)
constexpr int TILE = HIDN * ROWP;    // floats per warp tile

struct ResParams { int res[NLEV]; };

typedef unsigned long long u64;

__device__ __forceinline__ u64 pk2(float lo, float hi) {
    u64 r; asm("mov.b64 %0, {%1, %2};" : "=l"(r) : "f"(lo), "f"(hi)); return r;
}
__device__ __forceinline__ u64 dup2(float v) {
    u64 r; asm("mov.b64 %0, {%1, %1};" : "=l"(r) : "f"(v)); return r;
}
__device__ __forceinline__ void upk2(u64 v, float& lo, float& hi) {
    asm("mov.b64 {%0, %1}, %2;" : "=f"(lo), "=f"(hi) : "l"(v));
}
__device__ __forceinline__ void fma2(u64& acc, u64 a, u64 b) {
    asm("fma.rn.f32x2 %0, %1, %2, %0;" : "+l"(acc) : "l"(a), "l"(b));
}

__device__ __forceinline__ float selu_f(float v) {
    const float sc = 1.0507009873554805f;
    const float al = 1.6732632423543772f;
    return v > 0.0f ? sc * v : sc * (al * expm1f(v));
}

__global__ __launch_bounds__(BLK, 3)
void ngp_fused7_kernel(const float*  __restrict__ gx,     // [N,3]
                       const float*  __restrict__ gcr,    // [N]
                       const float4* __restrict__ gtab,   // [NLEV*TBL] float4
                       const float*  __restrict__ gW1,    // [40,64]
                       const float*  __restrict__ gb1,    // [64]
                       const float*  __restrict__ gW2,    // [64,64]
                       const float*  __restrict__ gb2,    // [64]
                       const float*  __restrict__ gW3,    // [64,13]
                       const float*  __restrict__ gb3,    // [13]
                       float*        __restrict__ gout,   // [N,13]
                       int N, ResParams rp)
{
    __shared__ float sW1[40 * HIDN];      // natural [k][j]
    __shared__ float sW2[HIDN * HIDN];
    __shared__ float sW3[HIDN * 16];      // rows padded 13 -> 16
    __shared__ float sB1[HIDN];
    __shared__ float sB2[HIDN];
    __shared__ float sB3[16];
    extern __shared__ float sT[];         // [4 warps][64][36] = 36 KB

    const int tid = threadIdx.x;
    for (int i = tid; i < 40 * HIDN; i += BLK) sW1[i] = gW1[i];
    for (int i = tid; i < HIDN * HIDN; i += BLK) sW2[i] = gW2[i];
    for (int i = tid; i < HIDN * 16; i += BLK) {
        int k = i >> 4, j = i & 15;
        sW3[i] = (j < OUTD) ? gW3[k * OUTD + j] : 0.0f;
    }
    if (tid < HIDN) { sB1[tid] = gb1[tid]; sB2[tid] = gb2[tid]; }
    if (tid < 16)   { sB3[tid] = (tid < OUTD) ? gb3[tid] : 0.0f; }
    __syncthreads();

    const int lane = tid & 31;
    const int wrp  = tid >> 5;
    float* tile = sT + wrp * TILE;
    const int warpBase = blockIdx.x * BLK + wrp * 32;

    // ================= encoding: point n = warpBase + lane =================
    {
        const int nr = warpBase + lane;
        const int n = (nr < N) ? nr : (N - 1);
        const float x0 = gx[3 * n + 0];
        const float x1 = gx[3 * n + 1];
        const float x2 = gx[3 * n + 2];
        const float crs = gcr[n] * 0.5f;

        #pragma unroll
        for (int l = 0; l < NLEV; l++) {
            const float rf = (float)rp.res[l];
            const float xs0 = x0 * rf, xs1 = x1 * rf, xs2 = x2 * rf;
            const float fb0 = floorf(xs0), fb1 = floorf(xs1), fb2 = floorf(xs2);
            const float f0 = xs0 - fb0, f1 = xs1 - fb1, f2 = xs2 - fb2;
            const float g0 = 1.0f - f0, g1 = 1.0f - f1, g2 = 1.0f - f2;
            const unsigned c0 = (unsigned)fb0, c1 = (unsigned)fb1, c2 = (unsigned)fb2;

            const unsigned hx0 = c0,               hx1 = c0 + 1u;
            const unsigned hy0 = c1 * 2654435761u, hy1 = hy0 + 2654435761u;
            const unsigned hz0 = c2 * 805459861u,  hz1 = hz0 + 805459861u;
            const float wyz00 = g1 * g2, wyz01 = g1 * f2;
            const float wyz10 = f1 * g2, wyz11 = f1 * f2;

            const float4* tb = gtab + (unsigned)(l * TBL);
            float a0 = 0.f, a1 = 0.f, a2 = 0.f, a3 = 0.f;
            #pragma unroll
            for (int c = 0; c < 8; c++) {
                const unsigned hx = (c & 4) ? hx1 : hx0;
                const unsigned hy = (c & 2) ? hy1 : hy0;
                const unsigned hz = (c & 1) ? hz1 : hz0;
                const unsigned idx = (hx ^ hy ^ hz) & (unsigned)(TBL - 1);
                const float4 t = __ldg(&tb[idx]);
                const float wyz = (c & 2) ? ((c & 1) ? wyz11 : wyz10)
                                          : ((c & 1) ? wyz01 : wyz00);
                const float w = ((c & 4) ? f0 : g0) * wyz;
                a0 = fmaf(w, t.x, a0);
                a1 = fmaf(w, t.y, a1);
                a2 = fmaf(w, t.z, a2);
                a3 = fmaf(w, t.w, a3);
            }
            float scal;
            if (l == 0) scal = 1.0f;      // erf(1/sqrt(1e-12)) == 1 in fp32
            else        scal = erff(rsqrtf(fmaxf((8.0f * (float)l) * crs, 1e-12f)));
            tile[(0 * 10 + l) * ROWP + lane] = a0 * scal;
            tile[(1 * 10 + l) * ROWP + lane] = a1 * scal;
            tile[(2 * 10 + l) * ROWP + lane] = a2 * scal;
            tile[(3 * 10 + l) * ROWP + lane] = a3 * scal;
        }
    }
    __syncwarp();

    // ================= warp-tiled MLP =================
    const int pg = lane >> 3;   // point group: points pg*8 .. pg*8+7
    const int jg = lane & 7;    // j group:     j      jg*8 .. jg*8+7
    const float* arow = tile + pg * 8;

    // ---- layer 1: 40 -> 64, SELU ----
    {
        u64 acc[8][4];
        {
            const u64* bp = reinterpret_cast<const u64*>(&sB1[jg * 8]);
            const u64 b0 = bp[0], b1 = bp[1], b2 = bp[2], b3 = bp[3];
            #pragma unroll
            for (int pp = 0; pp < 8; pp++) {
                acc[pp][0] = b0; acc[pp][1] = b1; acc[pp][2] = b2; acc[pp][3] = b3;
            }
        }
        #pragma unroll 8
        for (int k = 0; k < 40; k++) {
            const float4 a0 = *reinterpret_cast<const float4*>(arow + k * ROWP);
            const float4 a1 = *reinterpret_cast<const float4*>(arow + k * ROWP + 4);
            const u64* wr = reinterpret_cast<const u64*>(&sW1[k * HIDN + jg * 8]);
            const u64 w0 = wr[0], w1 = wr[1], w2 = wr[2], w3 = wr[3];
            const float av[8] = {a0.x, a0.y, a0.z, a0.w, a1.x, a1.y, a1.z, a1.w};
            #pragma unroll
            for (int pp = 0; pp < 8; pp++) {
                const u64 d = dup2(av[pp]);
                fma2(acc[pp][0], d, w0);
                fma2(acc[pp][1], d, w1);
                fma2(acc[pp][2], d, w2);
                fma2(acc[pp][3], d, w3);
            }
        }
        __syncwarp();   // all lanes done reading rows before overwrite
        float o[8][8];  // [jj][pp]
        #pragma unroll
        for (int pp = 0; pp < 8; pp++) {
            #pragma unroll
            for (int q = 0; q < 4; q++) {
                float s0, s1; upk2(acc[pp][q], s0, s1);
                o[2 * q + 0][pp] = selu_f(s0);
                o[2 * q + 1][pp] = selu_f(s1);
            }
        }
        #pragma unroll
        for (int jj = 0; jj < 8; jj++) {
            u64* dst = reinterpret_cast<u64*>(tile + (jg * 8 + jj) * ROWP + pg * 8);
            #pragma unroll
            for (int t = 0; t < 4; t++)
                dst[t] = pk2(o[jj][2 * t], o[jj][2 * t + 1]);
        }
        __syncwarp();
    }

    // ---- layer 2: 64 -> 64, SELU ----
    {
        u64 acc[8][4];
        {
            const u64* bp = reinterpret_cast<const u64*>(&sB2[jg * 8]);
            const u64 b0 = bp[0], b1 = bp[1], b2 = bp[2], b3 = bp[3];
            #pragma unroll
            for (int pp = 0; pp < 8; pp++) {
                acc[pp][0] = b0; acc[pp][1] = b1; acc[pp][2] = b2; acc[pp][3] = b3;
            }
        }
        #pragma unroll 8
        for (int k = 0; k < HIDN; k++) {
            const float4 a0 = *reinterpret_cast<const float4*>(arow + k * ROWP);
            const float4 a1 = *reinterpret_cast<const float4*>(arow + k * ROWP + 4);
            const u64* wr = reinterpret_cast<const u64*>(&sW2[k * HIDN + jg * 8]);
            const u64 w0 = wr[0], w1 = wr[1], w2 = wr[2], w3 = wr[3];
            const float av[8] = {a0.x, a0.y, a0.z, a0.w, a1.x, a1.y, a1.z, a1.w};
            #pragma unroll
            for (int pp = 0; pp < 8; pp++) {
                const u64 d = dup2(av[pp]);
                fma2(acc[pp][0], d, w0);
                fma2(acc[pp][1], d, w1);
                fma2(acc[pp][2], d, w2);
                fma2(acc[pp][3], d, w3);
            }
        }
        __syncwarp();
        float o[8][8];
        #pragma unroll
        for (int pp = 0; pp < 8; pp++) {
            #pragma unroll
            for (int q = 0; q < 4; q++) {
                float s0, s1; upk2(acc[pp][q], s0, s1);
                o[2 * q + 0][pp] = selu_f(s0);
                o[2 * q + 1][pp] = selu_f(s1);
            }
        }
        #pragma unroll
        for (int jj = 0; jj < 8; jj++) {
            u64* dst = reinterpret_cast<u64*>(tile + (jg * 8 + jj) * ROWP + pg * 8);
            #pragma unroll
            for (int t = 0; t < 4; t++)
                dst[t] = pk2(o[jj][2 * t], o[jj][2 * t + 1]);
        }
        __syncwarp();
    }

    // ---- layer 3: 64 -> 13 (rows padded to 16). Thread j = jg*2, jg*2+1 ----
    {
        u64 acc3[8];
        {
            const u64 b = *reinterpret_cast<const u64*>(&sB3[jg * 2]);
            #pragma unroll
            for (int pp = 0; pp < 8; pp++) acc3[pp] = b;
        }
        #pragma unroll 8
        for (int k = 0; k < HIDN; k++) {
            const float4 a0 = *reinterpret_cast<const float4*>(arow + k * ROWP);
            const float4 a1 = *reinterpret_cast<const float4*>(arow + k * ROWP + 4);
            const u64 w = *reinterpret_cast<const u64*>(&sW3[k * 16 + jg * 2]);
            const float av[8] = {a0.x, a0.y, a0.z, a0.w, a1.x, a1.y, a1.z, a1.w};
            #pragma unroll
            for (int pp = 0; pp < 8; pp++) {
                const u64 d = dup2(av[pp]);
                fma2(acc3[pp], d, w);
            }
        }
        const int j0 = jg * 2;
        #pragma unroll
        for (int pp = 0; pp < 8; pp++) {
            const int np = warpBase + pg * 8 + pp;
            if (np < N && j0 < OUTD) {
                float s0, s1; upk2(acc3[pp], s0, s1);
                float* op = gout + (size_t)np * OUTD;
                op[j0] = s0;
                if (j0 + 1 < OUTD) op[j0 + 1] = s1;
            }
        }
    }
}

extern "C" void kernel_launch(void* const* d_in, const int* in_sizes, int n_in,
                              void* d_out, int out_size) {
    const float*  x   = (const float*)d_in[0];
    const float*  cr  = (const float*)d_in[1];
    const float4* tab = (const float4*)d_in[2];
    const float*  W1  = (const float*)d_in[3];
    const float*  b1  = (const float*)d_in[4];
    const float*  W2  = (const float*)d_in[5];
    const float*  b2  = (const float*)d_in[6];
    const float*  W3  = (const float*)d_in[7];
    const float*  b3  = (const float*)d_in[8];
    float* out = (float*)d_out;

    const int N = in_sizes[0] / 3;

    // Reference resolutions, identical libm double sequence.
    ResParams rp;
    const double B = exp((log(16.0 * pow(2.0, 10.0)) - log(16.0)) / 9.0);
    for (int l = 0; l < NLEV; l++) {
        rp.res[l] = (int)floor(16.0 * pow(B, (double)l));
    }

    const int dynSmem = 4 * TILE * (int)sizeof(float);   // 36 KB
    static bool attr_set = false;
    if (!attr_set) {
        cudaFuncSetAttribute(ngp_fused7_kernel,
                             cudaFuncAttributeMaxDynamicSharedMemorySize, dynSmem);
        attr_set = true;
    }

    const int blocks = (N + BLK - 1) / BLK;
    ngp_fused7_kernel<<<blocks, BLK, dynSmem>>>(
        x, cr, tab, W1, b1, W2, b2, W3, b3, out, N, rp);
}

// round 16
// speedup vs baseline: 1.6206x; 1.6198x over previous
#include <cuda_runtime.h>
#include <math.h>

// iNGPDW: fused hash-grid encode + erf scaling + 40->64->64->13 SELU MLP.
// Key change: MLP weights/biases live in __constant__ memory. All weight
// loads are lane-invariant -> LDCU on the uniform port, which is a SEPARATE
// pipe from L1/LSU. This removes ~1900 weight-LDS wavefronts/warp from the
// L1 pipe (the measured bottleneck), leaving L1 to the irreducible random
// table gathers. Activations stage in a per-thread smem column (no barrier).
// Packed fma.rn.f32x2 throughout. SELU uses expm1f (cancellation-safe).

constexpr int NLEV = 10;
constexpr int TBL  = 1 << 16;
constexpr int HIDN = 64;
constexpr int OUTD = 13;
constexpr int BLK  = 256;

struct ResParams { int res[NLEV]; };

typedef unsigned long long u64;

__constant__ __align__(16) float cW1[40 * HIDN];   // [k][j] natural
__constant__ __align__(16) float cW2[HIDN * HIDN];
__constant__ __align__(16) float cW3[HIDN * 16];   // rows padded 13 -> 16
__constant__ __align__(16) float cB1[HIDN];
__constant__ __align__(16) float cB2[HIDN];
__constant__ __align__(16) float cB3[16];

__device__ __forceinline__ u64 dup2(float v) {
    u64 r; asm("mov.b64 %0, {%1, %1};" : "=l"(r) : "f"(v)); return r;
}
__device__ __forceinline__ void upk2(u64 v, float& lo, float& hi) {
    asm("mov.b64 {%0, %1}, %2;" : "=f"(lo), "=f"(hi) : "l"(v));
}
__device__ __forceinline__ void fma2(u64& acc, u64 a, u64 b) {
    asm("fma.rn.f32x2 %0, %1, %2, %0;" : "+l"(acc) : "l"(a), "l"(b));
}

__device__ __forceinline__ float selu_f(float v) {
    const float sc = 1.0507009873554805f;
    const float al = 1.6732632423543772f;
    return v > 0.0f ? sc * v : sc * (al * expm1f(v));
}

__global__ __launch_bounds__(BLK, 2)
void ngp_fused8_kernel(const float*  __restrict__ gx,     // [N,3]
                       const float*  __restrict__ gcr,    // [N]
                       const float4* __restrict__ gtab,   // [NLEV*TBL] float4
                       float*        __restrict__ gout,   // [N,13]
                       int N, ResParams rp)
{
    extern __shared__ float sA[];   // [64 rows][BLK cols] = 64 KB, column-private

    const int tid = threadIdx.x;
    const int n = blockIdx.x * BLK + tid;
    if (n >= N) return;

    const float x0 = gx[3 * n + 0];
    const float x1 = gx[3 * n + 1];
    const float x2 = gx[3 * n + 2];
    const float crs = gcr[n] * 0.5f;     // SCALE_MULTI

    // ---- hash-grid encoding + erf scaling: write h to own sA column ----
    // feature index k = d*10 + l, row k of sA.
    #pragma unroll 2
    for (int l = 0; l < NLEV; l++) {
        const float rf = (float)rp.res[l];
        const float xs0 = x0 * rf, xs1 = x1 * rf, xs2 = x2 * rf;
        const float fb0 = floorf(xs0), fb1 = floorf(xs1), fb2 = floorf(xs2);
        const float f0 = xs0 - fb0, f1 = xs1 - fb1, f2 = xs2 - fb2;
        const float g0 = 1.0f - f0, g1 = 1.0f - f1, g2 = 1.0f - f2;
        const unsigned c0 = (unsigned)fb0, c1 = (unsigned)fb1, c2 = (unsigned)fb2;

        const unsigned hx0 = c0,               hx1 = c0 + 1u;
        const unsigned hy0 = c1 * 2654435761u, hy1 = hy0 + 2654435761u;
        const unsigned hz0 = c2 * 805459861u,  hz1 = hz0 + 805459861u;
        const float wyz00 = g1 * g2, wyz01 = g1 * f2;
        const float wyz10 = f1 * g2, wyz11 = f1 * f2;

        const float4* tb = gtab + (unsigned)(l * TBL);
        float a0 = 0.f, a1 = 0.f, a2 = 0.f, a3 = 0.f;
        #pragma unroll
        for (int c = 0; c < 8; c++) {
            const unsigned hx = (c & 4) ? hx1 : hx0;
            const unsigned hy = (c & 2) ? hy1 : hy0;
            const unsigned hz = (c & 1) ? hz1 : hz0;
            const unsigned idx = (hx ^ hy ^ hz) & (unsigned)(TBL - 1);
            const float4 t = __ldg(&tb[idx]);
            const float wyz = (c & 2) ? ((c & 1) ? wyz11 : wyz10)
                                      : ((c & 1) ? wyz01 : wyz00);
            const float w = ((c & 4) ? f0 : g0) * wyz;
            a0 = fmaf(w, t.x, a0);
            a1 = fmaf(w, t.y, a1);
            a2 = fmaf(w, t.z, a2);
            a3 = fmaf(w, t.w, a3);
        }
        float scal;
        if (l == 0) scal = 1.0f;   // erf(1/sqrt(1e-12)) == 1 in fp32
        else        scal = erff(rsqrtf(fmaxf((8.0f * (float)l) * crs, 1e-12f)));
        sA[(0 * 10 + l) * BLK + tid] = a0 * scal;
        sA[(1 * 10 + l) * BLK + tid] = a1 * scal;
        sA[(2 * 10 + l) * BLK + tid] = a2 * scal;
        sA[(3 * 10 + l) * BLK + tid] = a3 * scal;
    }

    // ---- layer 1: 40 -> 64, SELU. Weights via LDCU (uniform port). ----
    {
        u64 acc[32];
        const u64* bp = reinterpret_cast<const u64*>(cB1);
        #pragma unroll
        for (int q = 0; q < 32; q++) acc[q] = bp[q];

        #pragma unroll 8
        for (int k = 0; k < 40; k++) {
            const u64 d = dup2(sA[k * BLK + tid]);
            const ulonglong2* wr = reinterpret_cast<const ulonglong2*>(&cW1[k * HIDN]);
            #pragma unroll
            for (int q2 = 0; q2 < 16; q2++) {
                const ulonglong2 w = wr[q2];
                fma2(acc[2 * q2 + 0], d, w.x);
                fma2(acc[2 * q2 + 1], d, w.y);
            }
        }
        // h rows fully consumed (within this thread) -> overwrite with act1
        #pragma unroll
        for (int q = 0; q < 32; q++) {
            float s0, s1; upk2(acc[q], s0, s1);
            sA[(2 * q + 0) * BLK + tid] = selu_f(s0);
            sA[(2 * q + 1) * BLK + tid] = selu_f(s1);
        }
    }

    // ---- layer 2: 64 -> 64, SELU ----
    {
        u64 acc[32];
        const u64* bp = reinterpret_cast<const u64*>(cB2);
        #pragma unroll
        for (int q = 0; q < 32; q++) acc[q] = bp[q];

        #pragma unroll 8
        for (int k = 0; k < HIDN; k++) {
            const u64 d = dup2(sA[k * BLK + tid]);
            const ulonglong2* wr = reinterpret_cast<const ulonglong2*>(&cW2[k * HIDN]);
            #pragma unroll
            for (int q2 = 0; q2 < 16; q2++) {
                const ulonglong2 w = wr[q2];
                fma2(acc[2 * q2 + 0], d, w.x);
                fma2(acc[2 * q2 + 1], d, w.y);
            }
        }
        #pragma unroll
        for (int q = 0; q < 32; q++) {
            float s0, s1; upk2(acc[q], s0, s1);
            sA[(2 * q + 0) * BLK + tid] = selu_f(s0);
            sA[(2 * q + 1) * BLK + tid] = selu_f(s1);
        }
    }

    // ---- layer 3: 64 -> 13, linear ----
    {
        u64 acc3[7];
        const u64* bp = reinterpret_cast<const u64*>(cB3);
        #pragma unroll
        for (int q = 0; q < 7; q++) acc3[q] = bp[q];

        #pragma unroll 8
        for (int k = 0; k < HIDN; k++) {
            const u64 d = dup2(sA[k * BLK + tid]);
            const u64* wr = reinterpret_cast<const u64*>(&cW3[k * 16]);
            #pragma unroll
            for (int q = 0; q < 7; q++) fma2(acc3[q], d, wr[q]);
        }
        float s[14];
        #pragma unroll
        for (int q = 0; q < 7; q++) upk2(acc3[q], s[2 * q], s[2 * q + 1]);

        float* op = gout + (size_t)n * OUTD;
        #pragma unroll
        for (int j = 0; j < OUTD; j++) op[j] = s[j];
    }
}

extern "C" void kernel_launch(void* const* d_in, const int* in_sizes, int n_in,
                              void* d_out, int out_size) {
    const float*  x   = (const float*)d_in[0];
    const float*  cr  = (const float*)d_in[1];
    const float4* tab = (const float4*)d_in[2];
    const float*  W1  = (const float*)d_in[3];
    const float*  b1  = (const float*)d_in[4];
    const float*  W2  = (const float*)d_in[5];
    const float*  b2  = (const float*)d_in[6];
    const float*  W3  = (const float*)d_in[7];
    const float*  b3  = (const float*)d_in[8];
    float* out = (float*)d_out;

    const int N = in_sizes[0] / 3;

    // Stage weights into the constant bank: D2D async copies (graph-legal).
    cudaMemcpyToSymbolAsync(cW1, W1, 40 * HIDN * sizeof(float), 0,
                            cudaMemcpyDeviceToDevice, 0);
    cudaMemcpyToSymbolAsync(cW2, W2, HIDN * HIDN * sizeof(float), 0,
                            cudaMemcpyDeviceToDevice, 0);
    cudaMemcpyToSymbolAsync(cB1, b1, HIDN * sizeof(float), 0,
                            cudaMemcpyDeviceToDevice, 0);
    cudaMemcpyToSymbolAsync(cB2, b2, HIDN * sizeof(float), 0,
                            cudaMemcpyDeviceToDevice, 0);
    cudaMemcpyToSymbolAsync(cB3, b3, OUTD * sizeof(float), 0,
                            cudaMemcpyDeviceToDevice, 0);
    // W3: pad rows 13 -> 16 floats with a single 2D copy.
    void* pW3 = nullptr;
    cudaGetSymbolAddress(&pW3, cW3);
    cudaMemcpy2DAsync(pW3, 16 * sizeof(float),
                      W3,  OUTD * sizeof(float),
                      OUTD * sizeof(float), HIDN,
                      cudaMemcpyDeviceToDevice, 0);

    // Reference resolutions, identical libm double sequence.
    ResParams rp;
    const double B = exp((log(16.0 * pow(2.0, 10.0)) - log(16.0)) / 9.0);
    for (int l = 0; l < NLEV; l++) {
        rp.res[l] = (int)floor(16.0 * pow(B, (double)l));
    }

    const int dynSmem = HIDN * BLK * (int)sizeof(float);   // 64 KB
    static bool attr_set = false;
    if (!attr_set) {
        cudaFuncSetAttribute(ngp_fused8_kernel,
                             cudaFuncAttributeMaxDynamicSharedMemorySize, dynSmem);
        attr_set = true;
    }

    const int blocks = (N + BLK - 1) / BLK;
    ngp_fused8_kernel<<<blocks, BLK, dynSmem>>>(x, cr, tab, out, N, rp);
}